// round 1
// baseline (speedup 1.0000x reference)
#include <cuda_runtime.h>
#include <cuda_bf16.h>
#include <cstdint>

#define B_SAMPLES 32768
#define N_CLASSES 10
#define UNIT 16
#define D_IN 160
#define H1_DIM 512
#define H2_DIM 1024
#define O_DIM 3072

// ---------------- scratch (static device allocations only) ----------------
__device__ __nv_bfloat16 g_vj[(size_t)B_SAMPLES * D_IN];
__device__ __nv_bfloat16 g_h1[(size_t)B_SAMPLES * H1_DIM];
__device__ __nv_bfloat16 g_h2[(size_t)B_SAMPLES * H2_DIM];
__device__ __nv_bfloat16 g_w1[(size_t)D_IN * H1_DIM];
__device__ __nv_bfloat16 g_w2[(size_t)H1_DIM * H2_DIM];
__device__ __nv_bfloat16 g_w3[(size_t)H2_DIM * O_DIM];

// ---------------- fp32 -> bf16 conversion ----------------
__global__ void f2bf_kernel(const float2* __restrict__ src,
                            __nv_bfloat162* __restrict__ dst, int n2) {
    int i = blockIdx.x * blockDim.x + threadIdx.x;
    int stride = gridDim.x * blockDim.x;
    for (; i < n2; i += stride) {
        float2 v = src[i];
        dst[i] = __floats2bfloat162_rn(v.x, v.y);
    }
}

// ---------------- capsule mask: keep argmax-norm capsule, emit bf16 [B,160] --
__global__ void mask_kernel(const float* __restrict__ x,
                            __nv_bfloat16* __restrict__ vj) {
    int b = blockIdx.x * blockDim.x + threadIdx.x;
    if (b >= B_SAMPLES) return;
    const float* xb = x + (size_t)b * D_IN;

    float best = -1.0f;
    int bi = 0;
#pragma unroll
    for (int c = 0; c < N_CLASSES; c++) {
        const float4* p = (const float4*)(xb + c * UNIT);
        float s = 0.f;
#pragma unroll
        for (int j = 0; j < 4; j++) {
            float4 v = p[j];
            s += v.x * v.x + v.y * v.y + v.z * v.z + v.w * v.w;
        }
        if (s > best) { best = s; bi = c; }
    }

    uint4* dst = (uint4*)(vj + (size_t)b * D_IN);
    const float4* pc = (const float4*)(xb + bi * UNIT);
#pragma unroll
    for (int j = 0; j < 20; j++) {  // 20 chunks of 8 bf16
        uint4 v = make_uint4(0u, 0u, 0u, 0u);
        if ((j >> 1) == bi) {
            float4 f0 = pc[(j & 1) * 2];
            float4 f1 = pc[(j & 1) * 2 + 1];
            __nv_bfloat162 h0 = __floats2bfloat162_rn(f0.x, f0.y);
            __nv_bfloat162 h1 = __floats2bfloat162_rn(f0.z, f0.w);
            __nv_bfloat162 h2 = __floats2bfloat162_rn(f1.x, f1.y);
            __nv_bfloat162 h3 = __floats2bfloat162_rn(f1.z, f1.w);
            v.x = *(const uint32_t*)&h0;
            v.y = *(const uint32_t*)&h1;
            v.z = *(const uint32_t*)&h2;
            v.w = *(const uint32_t*)&h3;
        }
        dst[j] = v;
    }
}

// ---------------- mma.sync helpers ----------------
__device__ __forceinline__ void ldm_x4(uint32_t& r0, uint32_t& r1,
                                       uint32_t& r2, uint32_t& r3,
                                       uint32_t addr) {
    asm volatile("ldmatrix.sync.aligned.m8n8.x4.shared.b16 {%0,%1,%2,%3}, [%4];\n"
                 : "=r"(r0), "=r"(r1), "=r"(r2), "=r"(r3)
                 : "r"(addr));
}

__device__ __forceinline__ void ldm_x4_t(uint32_t& r0, uint32_t& r1,
                                         uint32_t& r2, uint32_t& r3,
                                         uint32_t addr) {
    asm volatile("ldmatrix.sync.aligned.m8n8.x4.trans.shared.b16 {%0,%1,%2,%3}, [%4];\n"
                 : "=r"(r0), "=r"(r1), "=r"(r2), "=r"(r3)
                 : "r"(addr));
}

__device__ __forceinline__ void mma_bf16(float* c, const uint32_t* a,
                                         const uint32_t* b) {
    asm volatile(
        "mma.sync.aligned.m16n8k16.row.col.f32.bf16.bf16.f32 "
        "{%0,%1,%2,%3}, {%4,%5,%6,%7}, {%8,%9}, {%0,%1,%2,%3};\n"
        : "+f"(c[0]), "+f"(c[1]), "+f"(c[2]), "+f"(c[3])
        : "r"(a[0]), "r"(a[1]), "r"(a[2]), "r"(a[3]), "r"(b[0]), "r"(b[1]));
}

// ---------------- GEMM: C = act(A[M,K] @ B[K,N] + bias) ----------------
// ACT 0: relu -> bf16 out ; ACT 1: sigmoid -> fp32 out
// BM=128, BN=128, BK=32; 256 threads = 8 warps (2x4), warp tile 64x32.
// All problem dims divide exactly: no boundary predication.
template <int ACT>
__global__ __launch_bounds__(256) void gemm_kernel(
    const __nv_bfloat16* __restrict__ A,
    const __nv_bfloat16* __restrict__ Bm,
    const float* __restrict__ bias,
    void* __restrict__ Cout,
    int M, int N, int K) {
    constexpr int BM = 128, BN = 128, BK = 32;
    constexpr int APAD = 8, BPAD = 8;

    __shared__ __nv_bfloat16 As[BM][BK + APAD];
    __shared__ __nv_bfloat16 Bs[BK][BN + BPAD];

    const int tid = threadIdx.x;
    const int warp = tid >> 5;
    const int lane = tid & 31;
    const int warpM = warp >> 2;  // 0..1
    const int warpN = warp & 3;   // 0..3

    const int bm = blockIdx.y * BM;
    const int bn = blockIdx.x * BN;

    float acc[4][4][4];
#pragma unroll
    for (int mt = 0; mt < 4; mt++)
#pragma unroll
        for (int nt = 0; nt < 4; nt++)
#pragma unroll
            for (int r = 0; r < 4; r++) acc[mt][nt][r] = 0.f;

    const uint32_t asBase = (uint32_t)__cvta_generic_to_shared(&As[0][0]);
    const uint32_t bsBase = (uint32_t)__cvta_generic_to_shared(&Bs[0][0]);

    for (int k0 = 0; k0 < K; k0 += BK) {
        // Load A tile: 128x32 bf16 = 512 uint4 chunks
#pragma unroll
        for (int c = tid; c < 512; c += 256) {
            int r = c >> 2;
            int col = (c & 3) * 8;
            *(uint4*)&As[r][col] =
                *(const uint4*)&A[(size_t)(bm + r) * K + k0 + col];
        }
        // Load B tile: 32x128 bf16 = 512 uint4 chunks
#pragma unroll
        for (int c = tid; c < 512; c += 256) {
            int r = c >> 4;
            int col = (c & 15) * 8;
            *(uint4*)&Bs[r][col] =
                *(const uint4*)&Bm[(size_t)(k0 + r) * N + bn + col];
        }
        __syncthreads();

#pragma unroll
        for (int kk = 0; kk < BK; kk += 16) {
            uint32_t a[4][4];
#pragma unroll
            for (int mt = 0; mt < 4; mt++) {
                int row = warpM * 64 + mt * 16 + (lane & 15);
                int col = kk + ((lane >> 4) << 3);
                uint32_t addr = asBase + (uint32_t)(row * (BK + APAD) + col) * 2u;
                ldm_x4(a[mt][0], a[mt][1], a[mt][2], a[mt][3], addr);
            }
            uint32_t b[4][2];
#pragma unroll
            for (int g = 0; g < 2; g++) {
                int row = kk + (lane & 15);
                int col = warpN * 32 + g * 16 + ((lane >> 4) << 3);
                uint32_t addr = bsBase + (uint32_t)(row * (BN + BPAD) + col) * 2u;
                uint32_t r0, r1, r2, r3;
                ldm_x4_t(r0, r1, r2, r3, addr);
                b[2 * g][0] = r0;
                b[2 * g][1] = r1;
                b[2 * g + 1][0] = r2;
                b[2 * g + 1][1] = r3;
            }
#pragma unroll
            for (int mt = 0; mt < 4; mt++)
#pragma unroll
                for (int nt = 0; nt < 4; nt++)
                    mma_bf16(acc[mt][nt], a[mt], b[nt]);
        }
        __syncthreads();
    }

    // Epilogue
    const int lr = lane >> 2;        // 0..7
    const int lc = (lane & 3) * 2;   // 0,2,4,6
#pragma unroll
    for (int mt = 0; mt < 4; mt++) {
#pragma unroll
        for (int nt = 0; nt < 4; nt++) {
            int row0 = bm + warpM * 64 + mt * 16 + lr;
            int col = bn + warpN * 32 + nt * 8 + lc;
            float bz0 = bias[col];
            float bz1 = bias[col + 1];
            float v00 = acc[mt][nt][0] + bz0;
            float v01 = acc[mt][nt][1] + bz1;
            float v10 = acc[mt][nt][2] + bz0;
            float v11 = acc[mt][nt][3] + bz1;
            if (ACT == 0) {
                v00 = fmaxf(v00, 0.f);
                v01 = fmaxf(v01, 0.f);
                v10 = fmaxf(v10, 0.f);
                v11 = fmaxf(v11, 0.f);
                __nv_bfloat16* C = (__nv_bfloat16*)Cout;
                *(__nv_bfloat162*)&C[(size_t)row0 * N + col] =
                    __floats2bfloat162_rn(v00, v01);
                *(__nv_bfloat162*)&C[(size_t)(row0 + 8) * N + col] =
                    __floats2bfloat162_rn(v10, v11);
            } else {
                v00 = 1.f / (1.f + __expf(-v00));
                v01 = 1.f / (1.f + __expf(-v01));
                v10 = 1.f / (1.f + __expf(-v10));
                v11 = 1.f / (1.f + __expf(-v11));
                float* C = (float*)Cout;
                *(float2*)&C[(size_t)row0 * N + col] = make_float2(v00, v01);
                *(float2*)&C[(size_t)(row0 + 8) * N + col] = make_float2(v10, v11);
            }
        }
    }
}

// ---------------- launch ----------------
extern "C" void kernel_launch(void* const* d_in, const int* in_sizes, int n_in,
                              void* d_out, int out_size) {
    const float* x  = (const float*)d_in[0];
    // d_in[1] = target (unused)
    const float* W1 = (const float*)d_in[2];
    const float* b1 = (const float*)d_in[3];
    const float* W2 = (const float*)d_in[4];
    const float* b2 = (const float*)d_in[5];
    const float* W3 = (const float*)d_in[6];
    const float* b3 = (const float*)d_in[7];

    void *pvj, *ph1, *ph2, *pw1, *pw2, *pw3;
    cudaGetSymbolAddress(&pvj, g_vj);
    cudaGetSymbolAddress(&ph1, g_h1);
    cudaGetSymbolAddress(&ph2, g_h2);
    cudaGetSymbolAddress(&pw1, g_w1);
    cudaGetSymbolAddress(&pw2, g_w2);
    cudaGetSymbolAddress(&pw3, g_w3);
    __nv_bfloat16* vj  = (__nv_bfloat16*)pvj;
    __nv_bfloat16* h1  = (__nv_bfloat16*)ph1;
    __nv_bfloat16* h2  = (__nv_bfloat16*)ph2;
    __nv_bfloat16* w1b = (__nv_bfloat16*)pw1;
    __nv_bfloat16* w2b = (__nv_bfloat16*)pw2;
    __nv_bfloat16* w3b = (__nv_bfloat16*)pw3;

    // weights -> bf16 (cheap, deterministic per call)
    f2bf_kernel<<<128, 256>>>((const float2*)W1, (__nv_bfloat162*)w1b,
                              D_IN * H1_DIM / 2);
    f2bf_kernel<<<256, 256>>>((const float2*)W2, (__nv_bfloat162*)w2b,
                              H1_DIM * H2_DIM / 2);
    f2bf_kernel<<<512, 256>>>((const float2*)W3, (__nv_bfloat162*)w3b,
                              H2_DIM * O_DIM / 2);

    // capsule mask
    mask_kernel<<<B_SAMPLES / 256, 256>>>(x, vj);

    // MLP chain
    gemm_kernel<0><<<dim3(H1_DIM / 128, B_SAMPLES / 128), 256>>>(
        vj, w1b, b1, h1, B_SAMPLES, H1_DIM, D_IN);
    gemm_kernel<0><<<dim3(H2_DIM / 128, B_SAMPLES / 128), 256>>>(
        h1, w2b, b2, h2, B_SAMPLES, H2_DIM, H1_DIM);
    gemm_kernel<1><<<dim3(O_DIM / 128, B_SAMPLES / 128), 256>>>(
        h2, w3b, b3, d_out, B_SAMPLES, O_DIM, H2_DIM);
}

// round 3
// speedup vs baseline: 1.1676x; 1.1676x over previous
#include <cuda_runtime.h>
#include <cuda_bf16.h>
#include <cstdint>

#define B_SAMPLES 32768
#define N_CLASSES 10
#define UNIT 16
#define D_IN 160
#define H1_DIM 512
#define H2_DIM 1024
#define O_DIM 3072

// ---------------- scratch (static device allocations only) ----------------
__device__ __align__(128) __nv_bfloat16 g_vj[(size_t)B_SAMPLES * D_IN];
__device__ __align__(128) __nv_bfloat16 g_h1[(size_t)B_SAMPLES * H1_DIM];
__device__ __align__(128) __nv_bfloat16 g_h2[(size_t)B_SAMPLES * H2_DIM];
__device__ __align__(128) __nv_bfloat16 g_w1[(size_t)D_IN * H1_DIM];
__device__ __align__(128) __nv_bfloat16 g_w2[(size_t)H1_DIM * H2_DIM];
__device__ __align__(128) __nv_bfloat16 g_w3[(size_t)H2_DIM * O_DIM];

// ---------------- fp32 -> bf16 ----------------
__global__ void f2bf_kernel(const float2* __restrict__ src,
                            __nv_bfloat162* __restrict__ dst, int n2) {
    int i = blockIdx.x * blockDim.x + threadIdx.x;
    int stride = gridDim.x * blockDim.x;
    for (; i < n2; i += stride) {
        float2 v = src[i];
        dst[i] = __floats2bfloat162_rn(v.x, v.y);
    }
}

// ---------------- capsule mask (smem-staged, coalesced) ---------------------
__global__ __launch_bounds__(256) void mask_kernel(const float* __restrict__ x,
                                                   __nv_bfloat16* __restrict__ vj) {
    __shared__ float xs[64 * 168];
    __shared__ int bi[64];
    const int b0 = blockIdx.x * 64;

    const float4* src = (const float4*)(x + (size_t)b0 * D_IN);
    for (int q = threadIdx.x; q < 64 * 40; q += 256) {
        int s = q / 40, f = q % 40;
        *(float4*)&xs[s * 168 + f * 4] = src[q];
    }
    __syncthreads();

    if (threadIdx.x < 64) {
        const float* r = &xs[threadIdx.x * 168];
        float best = -1.f;
        int bidx = 0;
#pragma unroll
        for (int c = 0; c < N_CLASSES; c++) {
            float s = 0.f;
#pragma unroll
            for (int j = 0; j < UNIT; j++) {
                float v = r[c * UNIT + j];
                s += v * v;
            }
            if (s > best) { best = s; bidx = c; }
        }
        bi[threadIdx.x] = bidx;
    }
    __syncthreads();

    uint4* dst = (uint4*)(vj + (size_t)b0 * D_IN);
    for (int q = threadIdx.x; q < 64 * 20; q += 256) {
        int s = q / 20, j = q % 20;
        uint4 v = make_uint4(0u, 0u, 0u, 0u);
        int c = j >> 1;
        if (c == bi[s]) {
            const float* p = &xs[s * 168 + c * UNIT + (j & 1) * 8];
            __nv_bfloat162 h0 = __floats2bfloat162_rn(p[0], p[1]);
            __nv_bfloat162 h1 = __floats2bfloat162_rn(p[2], p[3]);
            __nv_bfloat162 h2 = __floats2bfloat162_rn(p[4], p[5]);
            __nv_bfloat162 h3 = __floats2bfloat162_rn(p[6], p[7]);
            v.x = *(uint32_t*)&h0; v.y = *(uint32_t*)&h1;
            v.z = *(uint32_t*)&h2; v.w = *(uint32_t*)&h3;
        }
        dst[q] = v;
    }
}

// ---------------- mma.sync helpers ----------------
__device__ __forceinline__ void ldm_x4(uint32_t& r0, uint32_t& r1,
                                       uint32_t& r2, uint32_t& r3,
                                       uint32_t addr) {
    asm volatile("ldmatrix.sync.aligned.m8n8.x4.shared.b16 {%0,%1,%2,%3}, [%4];\n"
                 : "=r"(r0), "=r"(r1), "=r"(r2), "=r"(r3)
                 : "r"(addr));
}

__device__ __forceinline__ void ldm_x4_t(uint32_t& r0, uint32_t& r1,
                                         uint32_t& r2, uint32_t& r3,
                                         uint32_t addr) {
    asm volatile("ldmatrix.sync.aligned.m8n8.x4.trans.shared.b16 {%0,%1,%2,%3}, [%4];\n"
                 : "=r"(r0), "=r"(r1), "=r"(r2), "=r"(r3)
                 : "r"(addr));
}

__device__ __forceinline__ void mma_bf16(float* c, const uint32_t* a,
                                         const uint32_t* b) {
    asm volatile(
        "mma.sync.aligned.m16n8k16.row.col.f32.bf16.bf16.f32 "
        "{%0,%1,%2,%3}, {%4,%5,%6,%7}, {%8,%9}, {%0,%1,%2,%3};\n"
        : "+f"(c[0]), "+f"(c[1]), "+f"(c[2]), "+f"(c[3])
        : "r"(a[0]), "r"(a[1]), "r"(a[2]), "r"(a[3]), "r"(b[0]), "r"(b[1]));
}

// ---------------- pipelined GEMM: C = act(A[M,K] @ B[K,N] + bias) -----------
// BM=128, BN=128, BK=32, 4-stage cp.async pipeline, 256 thr (8 warps 2x4),
// warp tile 64x32. All dims divide exactly.
#define BK 32
#define A_LDS 40   // 32 + 8 pad (halves)
#define B_LDS 136  // 128 + 8 pad (halves)
#define STAGES 4
#define A_STG (128 * A_LDS)             // halves per A stage
#define B_STG (BK * B_LDS)              // halves per B stage
#define SMEM_HALVES (STAGES * (A_STG + B_STG))
#define SMEM_BYTES (SMEM_HALVES * 2)

__device__ __forceinline__ void ld_stage(uint32_t sA, uint32_t sB,
                                         const __nv_bfloat16* __restrict__ A,
                                         const __nv_bfloat16* __restrict__ Bm,
                                         int bm, int bn, int K, int N, int t,
                                         int tid) {
    const __nv_bfloat16* Ag = A + (size_t)bm * K + t * BK;
    const __nv_bfloat16* Bg = Bm + (size_t)t * BK * N + bn;
#pragma unroll
    for (int i = 0; i < 2; i++) {
        int q = tid + i * 256;
        int ar = q >> 2, ac = (q & 3) * 8;
        asm volatile("cp.async.cg.shared.global [%0], [%1], 16;" ::
                     "r"(sA + (uint32_t)(ar * A_LDS + ac) * 2u),
                     "l"(Ag + (size_t)ar * K + ac));
        int br = q >> 4, bc = (q & 15) * 8;
        asm volatile("cp.async.cg.shared.global [%0], [%1], 16;" ::
                     "r"(sB + (uint32_t)(br * B_LDS + bc) * 2u),
                     "l"(Bg + (size_t)br * N + bc));
    }
    asm volatile("cp.async.commit_group;" ::: "memory");
}

template <int ACT>
__global__ __launch_bounds__(256, 2) void gemm_kernel(
    const __nv_bfloat16* __restrict__ A,
    const __nv_bfloat16* __restrict__ Bm,
    const float* __restrict__ bias,
    void* __restrict__ Cout,
    int M, int N, int K) {
    extern __shared__ __nv_bfloat16 smem[];

    const int tid = threadIdx.x;
    const int warp = tid >> 5;
    const int lane = tid & 31;
    const int warpM = warp >> 2;  // 0..1
    const int warpN = warp & 3;   // 0..3
    const int bm = blockIdx.y * 128;
    const int bn = blockIdx.x * 128;

    const uint32_t sBase = (uint32_t)__cvta_generic_to_shared(smem);
    const uint32_t aBase = sBase;
    const uint32_t bBase = sBase + (uint32_t)STAGES * A_STG * 2u;

    float acc[4][4][4];
#pragma unroll
    for (int mt = 0; mt < 4; mt++)
#pragma unroll
        for (int nt = 0; nt < 4; nt++)
#pragma unroll
            for (int r = 0; r < 4; r++) acc[mt][nt][r] = 0.f;

    const int T = K / BK;

    // prologue: prefetch 3 stages
#pragma unroll
    for (int t = 0; t < STAGES - 1; t++)
        ld_stage(aBase + (uint32_t)t * A_STG * 2u, bBase + (uint32_t)t * B_STG * 2u,
                 A, Bm, bm, bn, K, N, t, tid);

    for (int t = 0; t < T; t++) {
        asm volatile("cp.async.wait_group %0;" :: "n"(STAGES - 2) : "memory");
        __syncthreads();

        // issue next load first (overlaps with compute below)
        if (t + STAGES - 1 < T) {
            int sl = (t + STAGES - 1) & (STAGES - 1);
            ld_stage(aBase + (uint32_t)sl * A_STG * 2u,
                     bBase + (uint32_t)sl * B_STG * 2u,
                     A, Bm, bm, bn, K, N, t + STAGES - 1, tid);
        }

        const int s = t & (STAGES - 1);
        const uint32_t sA = aBase + (uint32_t)s * A_STG * 2u;
        const uint32_t sB = bBase + (uint32_t)s * B_STG * 2u;

#pragma unroll
        for (int kk = 0; kk < BK; kk += 16) {
            uint32_t a[4][4];
#pragma unroll
            for (int mt = 0; mt < 4; mt++) {
                int row = warpM * 64 + mt * 16 + (lane & 15);
                int col = kk + ((lane >> 4) << 3);
                ldm_x4(a[mt][0], a[mt][1], a[mt][2], a[mt][3],
                       sA + (uint32_t)(row * A_LDS + col) * 2u);
            }
            uint32_t b[4][2];
#pragma unroll
            for (int g = 0; g < 2; g++) {
                int row = kk + (lane & 15);
                int col = warpN * 32 + g * 16 + ((lane >> 4) << 3);
                uint32_t r0, r1, r2, r3;
                ldm_x4_t(r0, r1, r2, r3, sB + (uint32_t)(row * B_LDS + col) * 2u);
                b[2 * g][0] = r0; b[2 * g][1] = r1;
                b[2 * g + 1][0] = r2; b[2 * g + 1][1] = r3;
            }
#pragma unroll
            for (int mt = 0; mt < 4; mt++)
#pragma unroll
                for (int nt = 0; nt < 4; nt++)
                    mma_bf16(acc[mt][nt], a[mt], b[nt]);
        }
        __syncthreads();
    }

    // epilogue
    const int lr = lane >> 2;
    const int lc = (lane & 3) * 2;
#pragma unroll
    for (int mt = 0; mt < 4; mt++) {
#pragma unroll
        for (int nt = 0; nt < 4; nt++) {
            int row0 = bm + warpM * 64 + mt * 16 + lr;
            int col = bn + warpN * 32 + nt * 8 + lc;
            float bz0 = __ldg(bias + col);
            float bz1 = __ldg(bias + col + 1);
            float v00 = acc[mt][nt][0] + bz0;
            float v01 = acc[mt][nt][1] + bz1;
            float v10 = acc[mt][nt][2] + bz0;
            float v11 = acc[mt][nt][3] + bz1;
            if (ACT == 0) {
                v00 = fmaxf(v00, 0.f); v01 = fmaxf(v01, 0.f);
                v10 = fmaxf(v10, 0.f); v11 = fmaxf(v11, 0.f);
                __nv_bfloat16* C = (__nv_bfloat16*)Cout;
                *(__nv_bfloat162*)&C[(size_t)row0 * N + col] =
                    __floats2bfloat162_rn(v00, v01);
                *(__nv_bfloat162*)&C[(size_t)(row0 + 8) * N + col] =
                    __floats2bfloat162_rn(v10, v11);
            } else {
                v00 = 1.f / (1.f + __expf(-v00));
                v01 = 1.f / (1.f + __expf(-v01));
                v10 = 1.f / (1.f + __expf(-v10));
                v11 = 1.f / (1.f + __expf(-v11));
                float* C = (float*)Cout;
                *(float2*)&C[(size_t)row0 * N + col] = make_float2(v00, v01);
                *(float2*)&C[(size_t)(row0 + 8) * N + col] = make_float2(v10, v11);
            }
        }
    }
}

// ---------------- launch ----------------
extern "C" void kernel_launch(void* const* d_in, const int* in_sizes, int n_in,
                              void* d_out, int out_size) {
    const float* x  = (const float*)d_in[0];
    const float* W1 = (const float*)d_in[2];
    const float* b1 = (const float*)d_in[3];
    const float* W2 = (const float*)d_in[4];
    const float* b2 = (const float*)d_in[5];
    const float* W3 = (const float*)d_in[6];
    const float* b3 = (const float*)d_in[7];

    void *pvj, *ph1, *ph2, *pw1, *pw2, *pw3;
    cudaGetSymbolAddress(&pvj, g_vj);
    cudaGetSymbolAddress(&ph1, g_h1);
    cudaGetSymbolAddress(&ph2, g_h2);
    cudaGetSymbolAddress(&pw1, g_w1);
    cudaGetSymbolAddress(&pw2, g_w2);
    cudaGetSymbolAddress(&pw3, g_w3);
    __nv_bfloat16* vj  = (__nv_bfloat16*)pvj;
    __nv_bfloat16* h1  = (__nv_bfloat16*)ph1;
    __nv_bfloat16* h2  = (__nv_bfloat16*)ph2;
    __nv_bfloat16* w1b = (__nv_bfloat16*)pw1;
    __nv_bfloat16* w2b = (__nv_bfloat16*)pw2;
    __nv_bfloat16* w3b = (__nv_bfloat16*)pw3;

    cudaFuncSetAttribute(gemm_kernel<0>,
                         cudaFuncAttributeMaxDynamicSharedMemorySize, SMEM_BYTES);
    cudaFuncSetAttribute(gemm_kernel<1>,
                         cudaFuncAttributeMaxDynamicSharedMemorySize, SMEM_BYTES);

    f2bf_kernel<<<128, 256>>>((const float2*)W1, (__nv_bfloat162*)w1b,
                              D_IN * H1_DIM / 2);
    f2bf_kernel<<<256, 256>>>((const float2*)W2, (__nv_bfloat162*)w2b,
                              H1_DIM * H2_DIM / 2);
    f2bf_kernel<<<512, 256>>>((const float2*)W3, (__nv_bfloat162*)w3b,
                              H2_DIM * O_DIM / 2);

    mask_kernel<<<B_SAMPLES / 64, 256>>>(x, vj);

    gemm_kernel<0><<<dim3(H1_DIM / 128, B_SAMPLES / 128), 256, SMEM_BYTES>>>(
        vj, w1b, b1, h1, B_SAMPLES, H1_DIM, D_IN);
    gemm_kernel<0><<<dim3(H2_DIM / 128, B_SAMPLES / 128), 256, SMEM_BYTES>>>(
        h1, w2b, b2, h2, B_SAMPLES, H2_DIM, H1_DIM);
    gemm_kernel<1><<<dim3(O_DIM / 128, B_SAMPLES / 128), 256, SMEM_BYTES>>>(
        h2, w3b, b3, d_out, B_SAMPLES, O_DIM, H2_DIM);
}